// round 3
// baseline (speedup 1.0000x reference)
#include <cuda_runtime.h>
#include <cstdint>
#include <cstddef>

#define S_LEN 2048
#define E_DIM 1024
#define N_H   16
#define N_KVH 8
#define HD    64
#define N_REP 2
#define KV_E  (N_KVH * HD)   // 512

// ---------------------------------------------------------------------------
// Scratch (device globals — no allocation allowed)
// ---------------------------------------------------------------------------
__device__ float g_q [S_LEN * E_DIM];   // 8 MB
__device__ float g_k [S_LEN * KV_E];    // 4 MB
__device__ float g_v [S_LEN * KV_E];    // 4 MB
__device__ float g_vt[KV_E * S_LEN];    // 4 MB (V transposed: [n][s])
__device__ float g_ao[S_LEN * E_DIM];   // 8 MB

// ---------------------------------------------------------------------------
// helpers
// ---------------------------------------------------------------------------
__device__ __forceinline__ float tf32r(float x) {
    uint32_t r;
    asm("cvt.rna.tf32.f32 %0, %1;" : "=r"(r) : "f"(x));
    return __uint_as_float(r);
}

__device__ __forceinline__ void mma_tf32(float* d, const float* a, const float* b) {
    asm volatile(
        "mma.sync.aligned.m16n8k8.row.col.f32.tf32.tf32.f32 "
        "{%0,%1,%2,%3}, {%4,%5,%6,%7}, {%8,%9}, {%0,%1,%2,%3};"
        : "+f"(d[0]), "+f"(d[1]), "+f"(d[2]), "+f"(d[3])
        : "r"(__float_as_uint(a[0])), "r"(__float_as_uint(a[1])),
          "r"(__float_as_uint(a[2])), "r"(__float_as_uint(a[3])),
          "r"(__float_as_uint(b[0])), "r"(__float_as_uint(b[1])));
}

// ---------------------------------------------------------------------------
// tf32x3 NT GEMM on tensor cores (mma.sync):
//   C[m,n] = sum_k A[m,k] * B[n,k]  (+ bias[n])
// Per-head offsets: A += h*saH, B += (h/bDiv)*sbH, C += h*scH
// BM=128, BK=32, BN in {64,128}. 256 threads.
// Smem layout: K-major, [BK][BM+4] / [BK][BN+4] (conflict-free frag loads),
// hi/lo split tiles, double buffered.
// ---------------------------------------------------------------------------
template <int BN>
__global__ __launch_bounds__(256, 1)
void gemm_mma(int K,
              const float* __restrict__ A, int lda, int saH,
              const float* __restrict__ B, int ldb, int sbH, int bDiv,
              float* __restrict__ C, int ldc, long long scH,
              const float* __restrict__ bias)
{
    constexpr int BM = 128, BK = 32;
    constexpr int AP = BM + 4;            // 132
    constexpr int BP = BN + 4;
    constexpr int ASZ = BK * AP;          // floats
    constexpr int BSZ = BK * BP;
    constexpr int BUF = 2 * ASZ + 2 * BSZ;
    constexpr int WGN = BN / 32;          // warps along N
    constexpr int WGM = 8 / WGN;          // warps along M
    constexpr int WM  = BM / WGM;         // 64 or 32
    constexpr int MT  = WM / 16;          // 4 or 2
    constexpr int NT  = 4;                // 32 / 8

    extern __shared__ float sm[];

    const int tid  = threadIdx.x;
    const int wid  = tid >> 5;
    const int lane = tid & 31;
    const int wm0  = (wid % WGM) * WM;
    const int wn0  = (wid / WGM) * 32;
    const int lr   = lane >> 2;     // 0..7
    const int lc   = lane & 3;      // 0..3

    const int h = blockIdx.z;
    A += (size_t)h * saH;
    B += (size_t)(h / bDiv) * sbH;
    C += (size_t)h * scH;
    const int bm = blockIdx.y * BM;
    const int bn = blockIdx.x * BN;

    // producer mappings
    const int arow = tid >> 1;                 // 0..127
    const int ak0  = (tid & 1) * 16;           // 0 or 16
    constexpr int TPRB = 256 / BN;             // threads per B row (2 or 4)
    constexpr int FPTB = BN / 8;               // floats per thread (16 or 8)
    const int brow = tid / TPRB;               // 0..BN-1
    const int bk0  = (tid % TPRB) * FPTB;

    float4 ra[4];
    float4 rb[FPTB / 4];

    auto ldg = [&](int kt) {
        const float4* pa = reinterpret_cast<const float4*>(
            A + (size_t)(bm + arow) * lda + kt * BK + ak0);
        #pragma unroll
        for (int j = 0; j < 4; j++) ra[j] = pa[j];
        const float4* pb = reinterpret_cast<const float4*>(
            B + (size_t)(bn + brow) * ldb + kt * BK + bk0);
        #pragma unroll
        for (int j = 0; j < FPTB / 4; j++) rb[j] = pb[j];
    };

    auto sts = [&](int buf) {
        float* base = sm + buf * BUF;
        float* asH = base;
        float* asL = base + ASZ;
        float* bsH = base + 2 * ASZ;
        float* bsL = bsH + BSZ;
        #pragma unroll
        for (int j = 0; j < 4; j++) {
            const float e[4] = { ra[j].x, ra[j].y, ra[j].z, ra[j].w };
            #pragma unroll
            for (int t = 0; t < 4; t++) {
                int k = ak0 + j * 4 + t;
                float hi = tf32r(e[t]);
                asH[k * AP + arow] = hi;
                asL[k * AP + arow] = tf32r(e[t] - hi);
            }
        }
        #pragma unroll
        for (int j = 0; j < FPTB / 4; j++) {
            const float e[4] = { rb[j].x, rb[j].y, rb[j].z, rb[j].w };
            #pragma unroll
            for (int t = 0; t < 4; t++) {
                int k = bk0 + j * 4 + t;
                float hi = tf32r(e[t]);
                bsH[k * BP + brow] = hi;
                bsL[k * BP + brow] = tf32r(e[t] - hi);
            }
        }
    };

    float acc[MT][NT][4];
    #pragma unroll
    for (int i = 0; i < MT; i++)
        #pragma unroll
        for (int j = 0; j < NT; j++)
            #pragma unroll
            for (int t = 0; t < 4; t++) acc[i][j][t] = 0.0f;

    const int nk = K / BK;

    ldg(0);
    sts(0);
    __syncthreads();

    for (int kt = 0; kt < nk; kt++) {
        const int buf = kt & 1;
        if (kt + 1 < nk) ldg(kt + 1);

        float* base = sm + buf * BUF;
        float* asH = base;
        float* asL = base + ASZ;
        float* bsH = base + 2 * ASZ;
        float* bsL = bsH + BSZ;

        #pragma unroll
        for (int ks = 0; ks < BK / 8; ks++) {
            const int kk = ks * 8 + lc;
            float ah[MT][4], al[MT][4], bh[NT][2], bl[NT][2];
            #pragma unroll
            for (int mt = 0; mt < MT; mt++) {
                const int m = wm0 + mt * 16 + lr;
                ah[mt][0] = asH[kk * AP + m];
                ah[mt][1] = asH[kk * AP + m + 8];
                ah[mt][2] = asH[(kk + 4) * AP + m];
                ah[mt][3] = asH[(kk + 4) * AP + m + 8];
                al[mt][0] = asL[kk * AP + m];
                al[mt][1] = asL[kk * AP + m + 8];
                al[mt][2] = asL[(kk + 4) * AP + m];
                al[mt][3] = asL[(kk + 4) * AP + m + 8];
            }
            #pragma unroll
            for (int nt = 0; nt < NT; nt++) {
                const int n = wn0 + nt * 8 + lr;
                bh[nt][0] = bsH[kk * BP + n];
                bh[nt][1] = bsH[(kk + 4) * BP + n];
                bl[nt][0] = bsL[kk * BP + n];
                bl[nt][1] = bsL[(kk + 4) * BP + n];
            }
            #pragma unroll
            for (int mt = 0; mt < MT; mt++)
                #pragma unroll
                for (int nt = 0; nt < NT; nt++) {
                    mma_tf32(acc[mt][nt], ah[mt], bh[nt]);
                    mma_tf32(acc[mt][nt], ah[mt], bl[nt]);
                    mma_tf32(acc[mt][nt], al[mt], bh[nt]);
                }
        }

        if (kt + 1 < nk) sts(buf ^ 1);
        __syncthreads();
    }

    // Epilogue: direct float2 stores (+bias)
    #pragma unroll
    for (int mt = 0; mt < MT; mt++) {
        const int row = bm + wm0 + mt * 16 + lr;
        #pragma unroll
        for (int nt = 0; nt < NT; nt++) {
            const int col = bn + wn0 + nt * 8 + 2 * lc;
            float b0 = 0.0f, b1 = 0.0f;
            if (bias) { b0 = bias[col]; b1 = bias[col + 1]; }
            float2 v0 = make_float2(acc[mt][nt][0] + b0, acc[mt][nt][1] + b1);
            float2 v1 = make_float2(acc[mt][nt][2] + b0, acc[mt][nt][3] + b1);
            *reinterpret_cast<float2*>(&C[(size_t)row * ldc + col])       = v0;
            *reinterpret_cast<float2*>(&C[(size_t)(row + 8) * ldc + col]) = v1;
        }
    }
}

// ---------------------------------------------------------------------------
// RoPE (in-place on Q and K)
// ---------------------------------------------------------------------------
__global__ __launch_bounds__(256)
void rope_kernel(float* __restrict__ q, float* __restrict__ k,
                 const float* __restrict__ cosv, const float* __restrict__ sinv)
{
    int idx = blockIdx.x * blockDim.x + threadIdx.x;
    const int totq = S_LEN * N_H * (HD / 2);
    if (idx < totq) {
        int i = idx & 31;
        int h = (idx >> 5) & (N_H - 1);
        int s = idx >> 9;
        float c  = cosv[s * 32 + i];
        float sn = sinv[s * 32 + i];
        float* p = q + ((size_t)s * N_H + h) * HD + 2 * i;
        float xr = p[0], xi = p[1];
        p[0] = xr * c - xi * sn;
        p[1] = xr * sn + xi * c;
    } else {
        idx -= totq;
        if (idx < S_LEN * N_KVH * (HD / 2)) {
            int i = idx & 31;
            int h = (idx >> 5) & (N_KVH - 1);
            int s = idx >> 8;
            float c  = cosv[s * 32 + i];
            float sn = sinv[s * 32 + i];
            float* p = k + ((size_t)s * N_KVH + h) * HD + 2 * i;
            float xr = p[0], xi = p[1];
            p[0] = xr * c - xi * sn;
            p[1] = xr * sn + xi * c;
        }
    }
}

// ---------------------------------------------------------------------------
// V transpose: vt[n][s] = v[s][n]   (512 x 2048)
// ---------------------------------------------------------------------------
__global__ __launch_bounds__(256)
void transpose_v(const float* __restrict__ v, float* __restrict__ vt)
{
    __shared__ float t[32][33];
    const int bs = blockIdx.x * 32;
    const int bn = blockIdx.y * 32;
    const int x = threadIdx.x, y = threadIdx.y;
    #pragma unroll
    for (int i = y; i < 32; i += 8)
        t[i][x] = v[(size_t)(bs + i) * KV_E + bn + x];
    __syncthreads();
    #pragma unroll
    for (int i = y; i < 32; i += 8)
        vt[(size_t)(bn + i) * S_LEN + bs + x] = t[x][i];
}

// ---------------------------------------------------------------------------
// Softmax over key dim: scale, clamp, +bias, stable softmax (row len 2048)
// ---------------------------------------------------------------------------
__global__ __launch_bounds__(256)
void softmax_kernel(float* __restrict__ w, const float* __restrict__ bias)
{
    const int q = blockIdx.x;
    const int h = blockIdx.y;
    float* row       = w    + ((size_t)h * S_LEN + q) * S_LEN;
    const float* brw = bias + ((size_t)h * S_LEN + q) * S_LEN;

    const float scale = 0.125f;
    const int t = threadIdx.x;

    float vals[8];
    float m = -1e30f;
    #pragma unroll
    for (int i = 0; i < 8; i++) {
        int c = t + i * 256;
        float z = row[c] * scale;
        z = fminf(fmaxf(z, -50000.0f), 50000.0f) + brw[c];
        vals[i] = z;
        m = fmaxf(m, z);
    }

    __shared__ float red[8];
    #pragma unroll
    for (int o = 16; o; o >>= 1) m = fmaxf(m, __shfl_xor_sync(~0u, m, o));
    if ((t & 31) == 0) red[t >> 5] = m;
    __syncthreads();
    float bm = red[0];
    #pragma unroll
    for (int i = 1; i < 8; i++) bm = fmaxf(bm, red[i]);
    __syncthreads();

    float sum = 0.0f;
    #pragma unroll
    for (int i = 0; i < 8; i++) {
        vals[i] = __expf(vals[i] - bm);
        sum += vals[i];
    }
    #pragma unroll
    for (int o = 16; o; o >>= 1) sum += __shfl_xor_sync(~0u, sum, o);
    if ((t & 31) == 0) red[t >> 5] = sum;
    __syncthreads();
    float bs = 0.0f;
    #pragma unroll
    for (int i = 0; i < 8; i++) bs += red[i];
    float inv = 1.0f / bs;

    #pragma unroll
    for (int i = 0; i < 8; i++) row[t + i * 256] = vals[i] * inv;
}

// ---------------------------------------------------------------------------
extern "C" void kernel_launch(void* const* d_in, const int* in_sizes, int n_in,
                              void* d_out, int out_size)
{
    const float* x         = (const float*)d_in[0];
    const float* attn_bias = (const float*)d_in[1];
    const float* fcos      = (const float*)d_in[2];
    const float* fsin      = (const float*)d_in[3];
    const float* wq_w      = (const float*)d_in[4];
    const float* wk_w      = (const float*)d_in[5];
    const float* wk_b      = (const float*)d_in[6];
    const float* wv_w      = (const float*)d_in[7];
    const float* wv_b      = (const float*)d_in[8];
    const float* wo_w      = (const float*)d_in[9];
    const float* wo_b      = (const float*)d_in[10];

    float* out   = (float*)d_out;
    float* attnw = (float*)d_out + (size_t)S_LEN * E_DIM;

    float *q, *k, *v, *vt, *ao;
    cudaGetSymbolAddress((void**)&q,  g_q);
    cudaGetSymbolAddress((void**)&k,  g_k);
    cudaGetSymbolAddress((void**)&v,  g_v);
    cudaGetSymbolAddress((void**)&vt, g_vt);
    cudaGetSymbolAddress((void**)&ao, g_ao);

    // dynamic smem: 2 buffers * (2*32*(BM+4) + 2*32*(BN+4)) floats
    const int SM128 = 2 * (2 * 32 * 132 + 2 * 32 * 132) * 4;  // 135168
    const int SM64  = 2 * (2 * 32 * 132 + 2 * 32 * 68)  * 4;  // 102400
    cudaFuncSetAttribute(gemm_mma<128>, cudaFuncAttributeMaxDynamicSharedMemorySize, SM128);
    cudaFuncSetAttribute(gemm_mma<64>,  cudaFuncAttributeMaxDynamicSharedMemorySize, SM64);

    // 1-3. QKV projections (NT, tf32x3)
    gemm_mma<128><<<dim3(E_DIM / 128, S_LEN / 128, 1), 256, SM128>>>(E_DIM,
        x, E_DIM, 0, wq_w, E_DIM, 0, 1, q, E_DIM, 0, nullptr);
    gemm_mma<128><<<dim3(KV_E / 128, S_LEN / 128, 1), 256, SM128>>>(E_DIM,
        x, E_DIM, 0, wk_w, E_DIM, 0, 1, k, KV_E, 0, wk_b);
    gemm_mma<128><<<dim3(KV_E / 128, S_LEN / 128, 1), 256, SM128>>>(E_DIM,
        x, E_DIM, 0, wv_w, E_DIM, 0, 1, v, KV_E, 0, wv_b);

    // 4. RoPE
    {
        int tot = S_LEN * N_H * 32 + S_LEN * N_KVH * 32;
        rope_kernel<<<(tot + 255) / 256, 256>>>(q, k, fcos, fsin);
    }

    // 5. V transpose for NT PV
    transpose_v<<<dim3(S_LEN / 32, KV_E / 32), dim3(32, 8)>>>(v, vt);

    // 6. Scores: per head Q(2048x64) @ K^T -> raw dots into attnw
    gemm_mma<128><<<dim3(S_LEN / 128, S_LEN / 128, N_H), 256, SM128>>>(HD,
        q, E_DIM, HD,
        k, KV_E, HD, N_REP,
        attnw, S_LEN, (long long)S_LEN * S_LEN, nullptr);

    // 7. Softmax (scale, clamp, +bias) in place
    softmax_kernel<<<dim3(S_LEN, N_H), 256>>>(attnw, attn_bias);

    // 8. PV: attnw(2048x2048) @ Vt^T per head
    gemm_mma<64><<<dim3(1, S_LEN / 128, N_H), 256, SM64>>>(S_LEN,
        attnw, S_LEN, (int)(S_LEN * S_LEN),
        vt, S_LEN, HD * S_LEN, N_REP,
        ao, E_DIM, HD, nullptr);

    // 9. Output projection
    gemm_mma<128><<<dim3(E_DIM / 128, S_LEN / 128, 1), 256, SM128>>>(E_DIM,
        ao, E_DIM, 0, wo_w, E_DIM, 0, 1, out, E_DIM, 0, wo_b);
}

// round 5
// speedup vs baseline: 2.7783x; 2.7783x over previous
#include <cuda_runtime.h>
#include <cuda_fp16.h>
#include <cstdint>
#include <cstddef>

#define S_LEN 2048
#define E_DIM 1024
#define N_H   16
#define N_KVH 8
#define HD    64
#define N_REP 2
#define KV_E  (N_KVH * HD)   // 512

// ---------------------------------------------------------------------------
// Scratch (device globals — no allocation allowed)
// ---------------------------------------------------------------------------
__device__ float g_q [S_LEN * E_DIM];
__device__ float g_k [S_LEN * KV_E];
__device__ float g_v [S_LEN * KV_E];
__device__ float g_vt[KV_E * S_LEN];
__device__ float g_ao[S_LEN * E_DIM];

// ---------------------------------------------------------------------------
// helpers
// ---------------------------------------------------------------------------
__device__ __forceinline__ uint32_t smem_u32(const void* p) {
    uint32_t a;
    asm("{ .reg .u64 t; cvta.to.shared.u64 t, %1; cvt.u32.u64 %0, t; }" : "=r"(a) : "l"(p));
    return a;
}

__device__ __forceinline__ void ldsm_x4(uint32_t* r, uint32_t addr) {
    asm volatile("ldmatrix.sync.aligned.m8n8.x4.shared.b16 {%0,%1,%2,%3}, [%4];"
                 : "=r"(r[0]), "=r"(r[1]), "=r"(r[2]), "=r"(r[3]) : "r"(addr));
}
__device__ __forceinline__ void mma_f16(float* d, const uint32_t* a, const uint32_t* b) {
    asm volatile(
        "mma.sync.aligned.m16n8k16.row.col.f32.f16.f16.f32 "
        "{%0,%1,%2,%3}, {%4,%5,%6,%7}, {%8,%9}, {%0,%1,%2,%3};"
        : "+f"(d[0]), "+f"(d[1]), "+f"(d[2]), "+f"(d[3])
        : "r"(a[0]), "r"(a[1]), "r"(a[2]), "r"(a[3]), "r"(b[0]), "r"(b[1]));
}

__device__ __forceinline__ uint32_t pack_h2(half a, half b) {
    __half2 h = __halves2half2(a, b);
    return *reinterpret_cast<uint32_t*>(&h);
}
// split 8 floats into hi/lo fp16 uint4s
__device__ __forceinline__ void split8(const float* f, uint4& hi, uint4& lo) {
    half hs[8], ls[8];
    #pragma unroll
    for (int i = 0; i < 8; i++) {
        hs[i] = __float2half_rn(f[i]);
        ls[i] = __float2half_rn(f[i] - __half2float(hs[i]));
    }
    hi = make_uint4(pack_h2(hs[0], hs[1]), pack_h2(hs[2], hs[3]),
                    pack_h2(hs[4], hs[5]), pack_h2(hs[6], hs[7]));
    lo = make_uint4(pack_h2(ls[0], ls[1]), pack_h2(ls[2], ls[3]),
                    pack_h2(ls[4], ls[5]), pack_h2(ls[6], ls[7]));
}

// swizzle for 64B rows: XOR byte bits[5:4] with row bits[2:1]
#define ROWSWZ(row) ((((row) >> 1) & 3) << 4)

// ---------------------------------------------------------------------------
// fp16x2-split NT GEMM on tensor cores:
//   C[m,n] = sum_k A[m,k]*B[n,k] (+bias[n]),  ~22-bit mantissa accuracy
// BM=128, BK=32, BN in {64,128}. 256 threads. ldmatrix + SW64 swizzle.
// ---------------------------------------------------------------------------
template <int BN>
__global__ __launch_bounds__(256, 1)
void gemm_h2(int K,
             const float* __restrict__ A, int lda, int saH,
             const float* __restrict__ B, int ldb, int sbH, int bDiv,
             float* __restrict__ C, int ldc, long long scH,
             const float* __restrict__ bias)
{
    constexpr int BM = 128, BK = 32;
    constexpr int ATILE = BM * BK * 2;        // 8192 B (one of hi/lo)
    constexpr int BTILE = BN * BK * 2;        // 8192 or 4096
    constexpr int BUF = 2 * ATILE + 2 * BTILE;
    constexpr int WGN = BN / 32;              // warps along N
    constexpr int WGM = 8 / WGN;
    constexpr int WM  = BM / WGM;             // 64 or 32
    constexpr int MT  = WM / 16;              // 4 or 2
    constexpr int NT  = 4;                    // 32/8
    constexpr int NP  = 2;                    // n16 pairs per warp

    extern __shared__ char sm[];
    const uint32_t smb = smem_u32(sm);

    const int tid  = threadIdx.x;
    const int wid  = tid >> 5;
    const int lane = tid & 31;
    const int wm0  = (wid % WGM) * WM;
    const int wn0  = (wid / WGM) * 32;
    const int lr   = lane >> 2;
    const int lc   = lane & 3;
    const int lrow = lane & 7;
    const int sel  = lane >> 3;               // 0..3

    const int h = blockIdx.z;
    A += (size_t)h * saH;
    B += (size_t)(h / bDiv) * sbH;
    C += (size_t)h * scH;
    const int bm = blockIdx.y * BM;
    const int bn = blockIdx.x * BN;

    // producer mappings
    const int arow = tid >> 1;
    const int ak0  = (tid & 1) * 16;              // floats
    constexpr int TPRB = 256 / BN;                // 2 or 4
    constexpr int FPTB = BN / 8;                  // 16 or 8 floats/thread
    const int brow = tid / TPRB;
    const int bk0  = (tid % TPRB) * FPTB;

    float4 ra[4];
    float4 rb[FPTB / 4];

    auto ldg = [&](int kt) {
        const float4* pa = reinterpret_cast<const float4*>(
            A + (size_t)(bm + arow) * lda + kt * BK + ak0);
        #pragma unroll
        for (int j = 0; j < 4; j++) ra[j] = pa[j];
        const float4* pb = reinterpret_cast<const float4*>(
            B + (size_t)(bn + brow) * ldb + kt * BK + bk0);
        #pragma unroll
        for (int j = 0; j < FPTB / 4; j++) rb[j] = pb[j];
    };

    auto sts = [&](int buf) {
        char* base = sm + buf * BUF;
        // A: 16 floats -> two 16B chunks each of hi/lo
        {
            const int swz = ROWSWZ(arow);
            float f[8];
            uint4 hi, lo;
            f[0]=ra[0].x; f[1]=ra[0].y; f[2]=ra[0].z; f[3]=ra[0].w;
            f[4]=ra[1].x; f[5]=ra[1].y; f[6]=ra[1].z; f[7]=ra[1].w;
            split8(f, hi, lo);
            int c0 = (ak0 * 2) ^ swz;
            *reinterpret_cast<uint4*>(base + arow * 64 + c0)         = hi;
            *reinterpret_cast<uint4*>(base + ATILE + arow * 64 + c0) = lo;
            f[0]=ra[2].x; f[1]=ra[2].y; f[2]=ra[2].z; f[3]=ra[2].w;
            f[4]=ra[3].x; f[5]=ra[3].y; f[6]=ra[3].z; f[7]=ra[3].w;
            split8(f, hi, lo);
            int c1 = (ak0 * 2 + 16) ^ swz;
            *reinterpret_cast<uint4*>(base + arow * 64 + c1)         = hi;
            *reinterpret_cast<uint4*>(base + ATILE + arow * 64 + c1) = lo;
        }
        // B
        {
            char* bb = base + 2 * ATILE;
            const int swz = ROWSWZ(brow);
            #pragma unroll
            for (int j = 0; j < FPTB / 8; j++) {
                float f[8];
                f[0]=rb[2*j].x;   f[1]=rb[2*j].y;   f[2]=rb[2*j].z;   f[3]=rb[2*j].w;
                f[4]=rb[2*j+1].x; f[5]=rb[2*j+1].y; f[6]=rb[2*j+1].z; f[7]=rb[2*j+1].w;
                uint4 hi, lo;
                split8(f, hi, lo);
                int c = ((bk0 + j * 8) * 2) ^ swz;
                *reinterpret_cast<uint4*>(bb + brow * 64 + c)         = hi;
                *reinterpret_cast<uint4*>(bb + BTILE + brow * 64 + c) = lo;
            }
        }
    };

    float acc[MT][NT][4];
    #pragma unroll
    for (int i = 0; i < MT; i++)
        #pragma unroll
        for (int j = 0; j < NT; j++)
            #pragma unroll
            for (int t = 0; t < 4; t++) acc[i][j][t] = 0.0f;

    const int nk = K / BK;

    ldg(0);
    sts(0);
    __syncthreads();

    for (int kt = 0; kt < nk; kt++) {
        const int buf = kt & 1;
        if (kt + 1 < nk) ldg(kt + 1);

        const uint32_t aH = smb + buf * BUF;
        const uint32_t aL = aH + ATILE;
        const uint32_t bH = aH + 2 * ATILE;
        const uint32_t bL = bH + BTILE;

        #pragma unroll
        for (int ks = 0; ks < 2; ks++) {              // two k16 steps
            // A fragments: sel0:(m0,k0) sel1:(m8,k0) sel2:(m0,k8) sel3:(m8,k8)
            uint32_t ah[MT][4], al[MT][4];
            #pragma unroll
            for (int mt = 0; mt < MT; mt++) {
                int row = wm0 + mt * 16 + lrow + (sel & 1) * 8;
                int kb  = (ks * 32 + (sel >> 1) * 16) ^ ROWSWZ(row);
                ldsm_x4(ah[mt], aH + row * 64 + kb);
                ldsm_x4(al[mt], aL + row * 64 + kb);
            }
            // B fragments (NO trans — rows are n, k contiguous):
            // sel0:(n0,k0)->b0  sel1:(n0,k8)->b1  sel2:(n8,k0)->b2  sel3:(n8,k8)->b3
            uint32_t bh[NP][4], bl[NP][4];
            #pragma unroll
            for (int p = 0; p < NP; p++) {
                int row = wn0 + p * 16 + lrow + (sel >> 1) * 8;
                int kb  = (ks * 32 + (sel & 1) * 16) ^ ROWSWZ(row);
                ldsm_x4(bh[p], bH + row * 64 + kb);
                ldsm_x4(bl[p], bL + row * 64 + kb);
            }
            #pragma unroll
            for (int mt = 0; mt < MT; mt++)
                #pragma unroll
                for (int p = 0; p < NP; p++) {
                    mma_f16(acc[mt][2 * p],     ah[mt], bh[p]);
                    mma_f16(acc[mt][2 * p],     ah[mt], bl[p]);
                    mma_f16(acc[mt][2 * p],     al[mt], bh[p]);
                    mma_f16(acc[mt][2 * p + 1], ah[mt], bh[p] + 2);
                    mma_f16(acc[mt][2 * p + 1], ah[mt], bl[p] + 2);
                    mma_f16(acc[mt][2 * p + 1], al[mt], bh[p] + 2);
                }
        }

        if (kt + 1 < nk) sts(buf ^ 1);
        __syncthreads();
    }

    // Epilogue
    #pragma unroll
    for (int mt = 0; mt < MT; mt++) {
        const int row = bm + wm0 + mt * 16 + lr;
        #pragma unroll
        for (int nt = 0; nt < NT; nt++) {
            const int col = bn + wn0 + nt * 8 + 2 * lc;
            float b0 = 0.0f, b1 = 0.0f;
            if (bias) { b0 = bias[col]; b1 = bias[col + 1]; }
            float2 v0 = make_float2(acc[mt][nt][0] + b0, acc[mt][nt][1] + b1);
            float2 v1 = make_float2(acc[mt][nt][2] + b0, acc[mt][nt][3] + b1);
            *reinterpret_cast<float2*>(&C[(size_t)row * ldc + col])       = v0;
            *reinterpret_cast<float2*>(&C[(size_t)(row + 8) * ldc + col]) = v1;
        }
    }
}

// ---------------------------------------------------------------------------
// RoPE (in-place on Q and K)
// ---------------------------------------------------------------------------
__global__ __launch_bounds__(256)
void rope_kernel(float* __restrict__ q, float* __restrict__ k,
                 const float* __restrict__ cosv, const float* __restrict__ sinv)
{
    int idx = blockIdx.x * blockDim.x + threadIdx.x;
    const int totq = S_LEN * N_H * (HD / 2);
    if (idx < totq) {
        int i = idx & 31;
        int h = (idx >> 5) & (N_H - 1);
        int s = idx >> 9;
        float c  = cosv[s * 32 + i];
        float sn = sinv[s * 32 + i];
        float* p = q + ((size_t)s * N_H + h) * HD + 2 * i;
        float xr = p[0], xi = p[1];
        p[0] = xr * c - xi * sn;
        p[1] = xr * sn + xi * c;
    } else {
        idx -= totq;
        if (idx < S_LEN * N_KVH * (HD / 2)) {
            int i = idx & 31;
            int h = (idx >> 5) & (N_KVH - 1);
            int s = idx >> 8;
            float c  = cosv[s * 32 + i];
            float sn = sinv[s * 32 + i];
            float* p = k + ((size_t)s * N_KVH + h) * HD + 2 * i;
            float xr = p[0], xi = p[1];
            p[0] = xr * c - xi * sn;
            p[1] = xr * sn + xi * c;
        }
    }
}

// ---------------------------------------------------------------------------
// V transpose: vt[n][s] = v[s][n]   (512 x 2048)
// ---------------------------------------------------------------------------
__global__ __launch_bounds__(256)
void transpose_v(const float* __restrict__ v, float* __restrict__ vt)
{
    __shared__ float t[32][33];
    const int bs = blockIdx.x * 32;
    const int bn = blockIdx.y * 32;
    const int x = threadIdx.x, y = threadIdx.y;
    #pragma unroll
    for (int i = y; i < 32; i += 8)
        t[i][x] = v[(size_t)(bs + i) * KV_E + bn + x];
    __syncthreads();
    #pragma unroll
    for (int i = y; i < 32; i += 8)
        vt[(size_t)(bn + i) * S_LEN + bs + x] = t[x][i];
}

// ---------------------------------------------------------------------------
// Softmax: scale, clamp, +bias, stable softmax (row len 2048)
// ---------------------------------------------------------------------------
__global__ __launch_bounds__(256)
void softmax_kernel(float* __restrict__ w, const float* __restrict__ bias)
{
    const int q = blockIdx.x;
    const int h = blockIdx.y;
    float* row       = w    + ((size_t)h * S_LEN + q) * S_LEN;
    const float* brw = bias + ((size_t)h * S_LEN + q) * S_LEN;

    const float scale = 0.125f;
    const int t = threadIdx.x;

    float vals[8];
    float m = -1e30f;
    #pragma unroll
    for (int i = 0; i < 8; i++) {
        int c = t + i * 256;
        float z = row[c] * scale;
        z = fminf(fmaxf(z, -50000.0f), 50000.0f) + brw[c];
        vals[i] = z;
        m = fmaxf(m, z);
    }

    __shared__ float red[8];
    #pragma unroll
    for (int o = 16; o; o >>= 1) m = fmaxf(m, __shfl_xor_sync(~0u, m, o));
    if ((t & 31) == 0) red[t >> 5] = m;
    __syncthreads();
    float bm = red[0];
    #pragma unroll
    for (int i = 1; i < 8; i++) bm = fmaxf(bm, red[i]);
    __syncthreads();

    float sum = 0.0f;
    #pragma unroll
    for (int i = 0; i < 8; i++) {
        vals[i] = __expf(vals[i] - bm);
        sum += vals[i];
    }
    #pragma unroll
    for (int o = 16; o; o >>= 1) sum += __shfl_xor_sync(~0u, sum, o);
    if ((t & 31) == 0) red[t >> 5] = sum;
    __syncthreads();
    float bs = 0.0f;
    #pragma unroll
    for (int i = 0; i < 8; i++) bs += red[i];
    float inv = 1.0f / bs;

    #pragma unroll
    for (int i = 0; i < 8; i++) row[t + i * 256] = vals[i] * inv;
}

// ---------------------------------------------------------------------------
extern "C" void kernel_launch(void* const* d_in, const int* in_sizes, int n_in,
                              void* d_out, int out_size)
{
    const float* x         = (const float*)d_in[0];
    const float* attn_bias = (const float*)d_in[1];
    const float* fcos      = (const float*)d_in[2];
    const float* fsin      = (const float*)d_in[3];
    const float* wq_w      = (const float*)d_in[4];
    const float* wk_w      = (const float*)d_in[5];
    const float* wk_b      = (const float*)d_in[6];
    const float* wv_w      = (const float*)d_in[7];
    const float* wv_b      = (const float*)d_in[8];
    const float* wo_w      = (const float*)d_in[9];
    const float* wo_b      = (const float*)d_in[10];

    float* out   = (float*)d_out;
    float* attnw = (float*)d_out + (size_t)S_LEN * E_DIM;

    float *q, *k, *v, *vt, *ao;
    cudaGetSymbolAddress((void**)&q,  g_q);
    cudaGetSymbolAddress((void**)&k,  g_k);
    cudaGetSymbolAddress((void**)&v,  g_v);
    cudaGetSymbolAddress((void**)&vt, g_vt);
    cudaGetSymbolAddress((void**)&ao, g_ao);

    const int SM128 = 2 * (2 * 8192 + 2 * 8192);  // 65536
    const int SM64  = 2 * (2 * 8192 + 2 * 4096);  // 49152
    cudaFuncSetAttribute(gemm_h2<128>, cudaFuncAttributeMaxDynamicSharedMemorySize, SM128);
    cudaFuncSetAttribute(gemm_h2<64>,  cudaFuncAttributeMaxDynamicSharedMemorySize, SM64);

    // 1-3. QKV projections
    gemm_h2<128><<<dim3(E_DIM / 128, S_LEN / 128, 1), 256, SM128>>>(E_DIM,
        x, E_DIM, 0, wq_w, E_DIM, 0, 1, q, E_DIM, 0, nullptr);
    gemm_h2<128><<<dim3(KV_E / 128, S_LEN / 128, 1), 256, SM128>>>(E_DIM,
        x, E_DIM, 0, wk_w, E_DIM, 0, 1, k, KV_E, 0, wk_b);
    gemm_h2<128><<<dim3(KV_E / 128, S_LEN / 128, 1), 256, SM128>>>(E_DIM,
        x, E_DIM, 0, wv_w, E_DIM, 0, 1, v, KV_E, 0, wv_b);

    // 4. RoPE
    {
        int tot = S_LEN * N_H * 32 + S_LEN * N_KVH * 32;
        rope_kernel<<<(tot + 255) / 256, 256>>>(q, k, fcos, fsin);
    }

    // 5. V transpose
    transpose_v<<<dim3(S_LEN / 32, KV_E / 32), dim3(32, 8)>>>(v, vt);

    // 6. Scores: raw dots into attnw
    gemm_h2<128><<<dim3(S_LEN / 128, S_LEN / 128, N_H), 256, SM128>>>(HD,
        q, E_DIM, HD,
        k, KV_E, HD, N_REP,
        attnw, S_LEN, (long long)S_LEN * S_LEN, nullptr);

    // 7. Softmax
    softmax_kernel<<<dim3(S_LEN, N_H), 256>>>(attnw, attn_bias);

    // 8. PV
    gemm_h2<64><<<dim3(1, S_LEN / 128, N_H), 256, SM64>>>(S_LEN,
        attnw, S_LEN, (int)(S_LEN * S_LEN),
        vt, S_LEN, HD * S_LEN, N_REP,
        ao, E_DIM, HD, nullptr);

    // 9. Output projection
    gemm_h2<128><<<dim3(E_DIM / 128, S_LEN / 128, 1), 256, SM128>>>(E_DIM,
        ao, E_DIM, 0, wo_w, E_DIM, 0, 1, out, E_DIM, 0, wo_b);
}